// round 4
// baseline (speedup 1.0000x reference)
#include <cuda_runtime.h>
#include <cstdint>

#define EMBED   512
#define NHEAD   8
#define HDIM    64
#define BATCH   8
#define NTOK    1024
#define NROWS   (BATCH * NTOK)

// Scratch (device globals — allocation-free per harness rules)
__device__ float g_xn[NROWS * EMBED];                    // layernormed x, [B*N, C]
__device__ float g_q[BATCH * NHEAD * NTOK * HDIM];       // [b][h][n][d]
__device__ float g_k[BATCH * NHEAD * NTOK * HDIM];
__device__ float g_v[BATCH * NHEAD * NTOK * HDIM];
__device__ float g_o[NROWS * EMBED];                     // attn out, [B*N, C]

// ---------------------------------------------------------------------------
// 1. LayerNorm over channel dim. x is [B, C, N] (N = H*W). Writes g_xn [B*N, C].
//    16 tokens per CTA; coalesced reads (consecutive n), smem transpose,
//    coalesced writes (consecutive c).
// ---------------------------------------------------------------------------
__global__ __launch_bounds__(256) void ln_kernel(const float* __restrict__ x,
                                                 const float* __restrict__ gamma,
                                                 const float* __restrict__ beta) {
    __shared__ float tile[16 * 513];
    __shared__ float psum[256];
    __shared__ float psq[256];
    __shared__ float smean[16];
    __shared__ float srstd[16];
    int t   = threadIdx.x;
    int blk = blockIdx.x;                 // 512 blocks = B * N/16
    int b   = blk >> 6;
    int n0  = (blk & 63) << 4;
    const float* xb = x + (size_t)b * EMBED * NTOK + n0;
    int nl    = t & 15;
    int cbase = t >> 4;
    float s = 0.f, sq = 0.f;
    #pragma unroll 8
    for (int k = 0; k < 32; k++) {
        int c = cbase + (k << 4);
        float v = xb[c * NTOK + nl];
        tile[nl * 513 + c] = v;
        s += v; sq += v * v;
    }
    psum[t] = s; psq[t] = sq;
    __syncthreads();
    if (t < 16) {
        float ss = 0.f, ssq = 0.f;
        #pragma unroll
        for (int g = 0; g < 16; g++) { ss += psum[t + (g << 4)]; ssq += psq[t + (g << 4)]; }
        float mu  = ss * (1.0f / EMBED);
        float var = ssq * (1.0f / EMBED) - mu * mu;
        smean[t] = mu;
        srstd[t] = rsqrtf(var + 1e-5f);
    }
    __syncthreads();
    float* dst = g_xn + (size_t)(b * NTOK + n0) * EMBED;
    #pragma unroll 8
    for (int k = 0; k < 32; k++) {
        int idx = t + (k << 8);
        int n = idx >> 9;
        int c = idx & 511;
        dst[n * EMBED + c] = (tile[n * 513 + c] - smean[n]) * srstd[n] * gamma[c] + beta[c];
    }
}

// ---------------------------------------------------------------------------
// 2. QKV GEMM: [8192,512] @ [512,1536] + bias, scattered into g_q/g_k/g_v.
//    128x128 block tile, BK=8, 8x8 per-thread micro-tile.
// ---------------------------------------------------------------------------
__global__ __launch_bounds__(256, 2) void qkv_gemm(const float* __restrict__ W,
                                                   const float* __restrict__ bias) {
    __shared__ float As[8][132];
    __shared__ float Bs[8][132];
    int t  = threadIdx.x;
    int bx = blockIdx.x;                  // 12 (cols of 128 over 1536)
    int by = blockIdx.y;                  // 64 (rows of 128 over 8192)
    int arow = t >> 1, acol = (t & 1) << 2;
    int brow = t >> 5, bcol = (t & 31) << 2;
    int tm   = (t >> 4) << 3, tn = (t & 15) << 3;
    const float* Ag = g_xn + (size_t)(by * 128) * EMBED;
    const float* Bg = W + bx * 128;
    float acc[8][8];
    #pragma unroll
    for (int i = 0; i < 8; i++)
        #pragma unroll
        for (int j = 0; j < 8; j++) acc[i][j] = 0.f;

    for (int k0 = 0; k0 < EMBED; k0 += 8) {
        float4 av = *(const float4*)&Ag[arow * EMBED + k0 + acol];
        float4 bv = *(const float4*)&Bg[(k0 + brow) * 1536 + bcol];
        __syncthreads();
        As[acol + 0][arow] = av.x;
        As[acol + 1][arow] = av.y;
        As[acol + 2][arow] = av.z;
        As[acol + 3][arow] = av.w;
        *(float4*)&Bs[brow][bcol] = bv;
        __syncthreads();
        #pragma unroll
        for (int kk = 0; kk < 8; kk++) {
            float a[8], bb[8];
            *(float4*)&a[0]  = *(const float4*)&As[kk][tm];
            *(float4*)&a[4]  = *(const float4*)&As[kk][tm + 4];
            *(float4*)&bb[0] = *(const float4*)&Bs[kk][tn];
            *(float4*)&bb[4] = *(const float4*)&Bs[kk][tn + 4];
            #pragma unroll
            for (int i = 0; i < 8; i++)
                #pragma unroll
                for (int j = 0; j < 8; j++)
                    acc[i][j] += a[i] * bb[j];
        }
    }
    // Epilogue: col j in [0,1536) = s*512 + h*64 + d; row = b*1024 + n
    int col0 = bx * 128 + tn;
    int sid  = col0 >> 9;
    int rem  = col0 & 511;
    int h    = rem >> 6;
    int d0   = rem & 63;
    int M0   = by * 128 + tm;
    int b    = M0 >> 10;
    int nb   = M0 & 1023;
    float* dst = (sid == 0) ? g_q : (sid == 1) ? g_k : g_v;
    dst += (size_t)((b * NHEAD + h) * NTOK + nb) * HDIM + d0;
    float bsv[8];
    #pragma unroll
    for (int j = 0; j < 8; j++) bsv[j] = bias[col0 + j];
    #pragma unroll
    for (int i = 0; i < 8; i++) {
        float4 v0 = make_float4(acc[i][0] + bsv[0], acc[i][1] + bsv[1],
                                acc[i][2] + bsv[2], acc[i][3] + bsv[3]);
        float4 v1 = make_float4(acc[i][4] + bsv[4], acc[i][5] + bsv[5],
                                acc[i][6] + bsv[6], acc[i][7] + bsv[7]);
        *(float4*)&dst[i * HDIM]     = v0;
        *(float4*)&dst[i * HDIM + 4] = v1;
    }
}

// ---------------------------------------------------------------------------
// 3. Flash attention fp32. CTA = (query-tile of 128, b*h). 16 KV tiles of 64.
//    Thread (tx in [0,16), ty in [0,16)): S rows ty*8..+7, S cols {tx+16j},
//    O cols tx*4..+3. Smem rows padded to 68 floats (conflict-free).
// ---------------------------------------------------------------------------
__global__ __launch_bounds__(256, 2) void flash_kernel() {
    extern __shared__ float sm[];
    float* Qs = sm;                 // 128*68
    float* Ks = Qs + 128 * 68;      // 64*68
    float* Vs = Ks + 64 * 68;       // 64*68
    float* Ps = Vs + 64 * 68;       // 128*68
    int t  = threadIdx.x;
    int tx = t & 15, ty = t >> 4;
    int qt = blockIdx.x;            // 8 query tiles
    int bh = blockIdx.y;            // 64 = B*h
    const float* Qg = g_q + (size_t)bh * NTOK * HDIM + qt * 128 * HDIM;
    const float* Kg = g_k + (size_t)bh * NTOK * HDIM;
    const float* Vg = g_v + (size_t)bh * NTOK * HDIM;

    #pragma unroll
    for (int li = 0; li < 8; li++) {      // load Q tile, fold in 1/sqrt(d)
        int lin = t + (li << 8);
        int row = lin >> 4;
        int d4  = (lin & 15) << 2;
        float4 v = *(const float4*)&Qg[row * HDIM + d4];
        v.x *= 0.125f; v.y *= 0.125f; v.z *= 0.125f; v.w *= 0.125f;
        *(float4*)&Qs[row * 68 + d4] = v;
    }

    float m[8], l[8], o[8][4];
    #pragma unroll
    for (int i = 0; i < 8; i++) {
        m[i] = -1e30f; l[i] = 0.f;
        #pragma unroll
        for (int j = 0; j < 4; j++) o[i][j] = 0.f;
    }

    for (int kt = 0; kt < 16; kt++) {
        __syncthreads();   // guards K/V/Ps reuse from prev iter (and Qs at kt=0)
        const float* kb = Kg + kt * 64 * HDIM;
        const float* vb = Vg + kt * 64 * HDIM;
        #pragma unroll
        for (int li = 0; li < 4; li++) {
            int lin = t + (li << 8);
            int row = lin >> 4;
            int d4  = (lin & 15) << 2;
            *(float4*)&Ks[row * 68 + d4] = *(const float4*)&kb[row * HDIM + d4];
            *(float4*)&Vs[row * 68 + d4] = *(const float4*)&vb[row * HDIM + d4];
        }
        __syncthreads();

        // S = Q Kᵀ  (per thread: 8 rows x 4 cols, cols = tx + 16j)
        float s[8][4];
        #pragma unroll
        for (int i = 0; i < 8; i++)
            #pragma unroll
            for (int j = 0; j < 4; j++) s[i][j] = 0.f;
        #pragma unroll
        for (int kk4 = 0; kk4 < 16; kk4++) {
            float4 kf[4];
            #pragma unroll
            for (int j = 0; j < 4; j++)
                kf[j] = *(const float4*)&Ks[(tx + (j << 4)) * 68 + (kk4 << 2)];
            #pragma unroll
            for (int i = 0; i < 8; i++) {
                float4 qf = *(const float4*)&Qs[((ty << 3) + i) * 68 + (kk4 << 2)];
                #pragma unroll
                for (int j = 0; j < 4; j++)
                    s[i][j] += qf.x * kf[j].x + qf.y * kf[j].y +
                               qf.z * kf[j].z + qf.w * kf[j].w;
            }
        }

        // Online softmax: 16-lane shuffle reductions (threads sharing ty share rows)
        #pragma unroll
        for (int i = 0; i < 8; i++) {
            float mx = fmaxf(fmaxf(s[i][0], s[i][1]), fmaxf(s[i][2], s[i][3]));
            #pragma unroll
            for (int off = 8; off >= 1; off >>= 1)
                mx = fmaxf(mx, __shfl_xor_sync(0xFFFFFFFFu, mx, off));
            float mn   = fmaxf(m[i], mx);
            float corr = __expf(m[i] - mn);
            float rs = 0.f;
            #pragma unroll
            for (int j = 0; j < 4; j++) {
                float p = __expf(s[i][j] - mn);
                Ps[((ty << 3) + i) * 68 + tx + (j << 4)] = p;
                rs += p;
            }
            #pragma unroll
            for (int off = 8; off >= 1; off >>= 1)
                rs += __shfl_xor_sync(0xFFFFFFFFu, rs, off);
            l[i] = l[i] * corr + rs;
            m[i] = mn;
            #pragma unroll
            for (int j = 0; j < 4; j++) o[i][j] *= corr;
        }
        __syncthreads();   // Ps complete before cross-thread PV reads

        // O += P V  (per thread: 8 rows x 4 O-cols, O-cols = tx*4..+3)
        #pragma unroll
        for (int c4 = 0; c4 < 16; c4++) {
            float4 v0 = *(const float4*)&Vs[((c4 << 2) + 0) * 68 + (tx << 2)];
            float4 v1 = *(const float4*)&Vs[((c4 << 2) + 1) * 68 + (tx << 2)];
            float4 v2 = *(const float4*)&Vs[((c4 << 2) + 2) * 68 + (tx << 2)];
            float4 v3 = *(const float4*)&Vs[((c4 << 2) + 3) * 68 + (tx << 2)];
            #pragma unroll
            for (int i = 0; i < 8; i++) {
                float4 p = *(const float4*)&Ps[((ty << 3) + i) * 68 + (c4 << 2)];
                o[i][0] += p.x * v0.x + p.y * v1.x + p.z * v2.x + p.w * v3.x;
                o[i][1] += p.x * v0.y + p.y * v1.y + p.z * v2.y + p.w * v3.y;
                o[i][2] += p.x * v0.z + p.y * v1.z + p.z * v2.z + p.w * v3.z;
                o[i][3] += p.x * v0.w + p.y * v1.w + p.z * v2.w + p.w * v3.w;
            }
        }
    }

    // Write O / l to g_o in [B*N, C] layout (c = h*64 + d)
    int b = bh >> 3, h = bh & 7;
    float* ob = g_o + (size_t)(b * NTOK + qt * 128 + (ty << 3)) * EMBED
              + h * HDIM + (tx << 2);
    #pragma unroll
    for (int i = 0; i < 8; i++) {
        float inv = 1.0f / l[i];
        float4 ov = make_float4(o[i][0] * inv, o[i][1] * inv,
                                o[i][2] * inv, o[i][3] * inv);
        *(float4*)&ob[i * EMBED] = ov;
    }
}

// ---------------------------------------------------------------------------
// 4. Output projection: [8192,512] @ [512,512] + bias, write [B, C, N].
// ---------------------------------------------------------------------------
__global__ __launch_bounds__(256, 2) void proj_gemm(const float* __restrict__ W,
                                                    const float* __restrict__ bias,
                                                    float* __restrict__ out) {
    __shared__ float As[8][132];
    __shared__ float Bs[8][132];
    int t  = threadIdx.x;
    int bx = blockIdx.x;                  // 4
    int by = blockIdx.y;                  // 64
    int arow = t >> 1, acol = (t & 1) << 2;
    int brow = t >> 5, bcol = (t & 31) << 2;
    int tm   = (t >> 4) << 3, tn = (t & 15) << 3;
    const float* Ag = g_o + (size_t)(by * 128) * EMBED;
    const float* Bg = W + bx * 128;
    float acc[8][8];
    #pragma unroll
    for (int i = 0; i < 8; i++)
        #pragma unroll
        for (int j = 0; j < 8; j++) acc[i][j] = 0.f;

    for (int k0 = 0; k0 < EMBED; k0 += 8) {
        float4 av = *(const float4*)&Ag[arow * EMBED + k0 + acol];
        float4 bv = *(const float4*)&Bg[(k0 + brow) * EMBED + bcol];
        __syncthreads();
        As[acol + 0][arow] = av.x;
        As[acol + 1][arow] = av.y;
        As[acol + 2][arow] = av.z;
        As[acol + 3][arow] = av.w;
        *(float4*)&Bs[brow][bcol] = bv;
        __syncthreads();
        #pragma unroll
        for (int kk = 0; kk < 8; kk++) {
            float a[8], bb[8];
            *(float4*)&a[0]  = *(const float4*)&As[kk][tm];
            *(float4*)&a[4]  = *(const float4*)&As[kk][tm + 4];
            *(float4*)&bb[0] = *(const float4*)&Bs[kk][tn];
            *(float4*)&bb[4] = *(const float4*)&Bs[kk][tn + 4];
            #pragma unroll
            for (int i = 0; i < 8; i++)
                #pragma unroll
                for (int j = 0; j < 8; j++)
                    acc[i][j] += a[i] * bb[j];
        }
    }
    // Epilogue: out[b, c, n] = acc + bias[c]  (transposed scatter)
    int col0 = bx * 128 + tn;
    int M0   = by * 128 + tm;
    int b    = M0 >> 10;
    int nb   = M0 & 1023;
    #pragma unroll
    for (int j = 0; j < 8; j++) {
        float bj = bias[col0 + j];
        float* op = out + ((size_t)b * EMBED + col0 + j) * NTOK + nb;
        #pragma unroll
        for (int i = 0; i < 8; i++)
            op[i] = acc[i][j] + bj;
    }
}

// ---------------------------------------------------------------------------
extern "C" void kernel_launch(void* const* d_in, const int* in_sizes, int n_in,
                              void* d_out, int out_size) {
    (void)in_sizes; (void)n_in; (void)out_size;
    const float* x      = (const float*)d_in[0];
    const float* gamma  = (const float*)d_in[1];
    const float* beta   = (const float*)d_in[2];
    const float* w_qkv  = (const float*)d_in[3];
    const float* b_qkv  = (const float*)d_in[4];
    const float* w_proj = (const float*)d_in[5];
    const float* b_proj = (const float*)d_in[6];
    float* out = (float*)d_out;

    ln_kernel<<<512, 256>>>(x, gamma, beta);
    qkv_gemm<<<dim3(12, 64), 256>>>(w_qkv, b_qkv);

    const int FLASH_SMEM = (128 * 68 + 64 * 68 + 64 * 68 + 128 * 68) * 4; // 104448 B
    cudaFuncSetAttribute(flash_kernel,
                         cudaFuncAttributeMaxDynamicSharedMemorySize, FLASH_SMEM);
    flash_kernel<<<dim3(8, 64), 256, FLASH_SMEM>>>();

    proj_gemm<<<dim3(4, 64), 256>>>(w_proj, b_proj, out);
}

// round 8
// speedup vs baseline: 3.1683x; 3.1683x over previous
#include <cuda_runtime.h>
#include <cstdint>

#define EMBED   512
#define NHEAD   8
#define HDIM    64
#define BATCH   8
#define NTOK    1024
#define NROWS   (BATCH * NTOK)

// Scratch (device globals — allocation-free per harness rules)
__device__ float g_xn[NROWS * EMBED];                    // layernormed x, [B*N, C]
__device__ float g_q[BATCH * NHEAD * NTOK * HDIM];       // [b][h][n][d]
__device__ float g_k[BATCH * NHEAD * NTOK * HDIM];
__device__ float g_v[BATCH * NHEAD * NTOK * HDIM];
__device__ float g_o[NROWS * EMBED];                     // attn out, [B*N, C]

// ---------------------------------------------------------------------------
// helpers: tf32 convert + m16n8k8 tf32 mma + fast exp2
// ---------------------------------------------------------------------------
__device__ __forceinline__ uint32_t f2tf32(float x) {
    uint32_t r;
    asm("cvt.rna.tf32.f32 %0, %1;" : "=r"(r) : "f"(x));
    return r;
}
__device__ __forceinline__ uint4 f4_to_tf32(float4 v) {
    uint4 u;
    u.x = f2tf32(v.x); u.y = f2tf32(v.y); u.z = f2tf32(v.z); u.w = f2tf32(v.w);
    return u;
}
__device__ __forceinline__ void mma_tf32(float c[4],
                                         uint32_t a0, uint32_t a1, uint32_t a2, uint32_t a3,
                                         uint32_t b0, uint32_t b1) {
    asm volatile(
        "mma.sync.aligned.m16n8k8.row.col.f32.tf32.tf32.f32 "
        "{%0,%1,%2,%3}, {%4,%5,%6,%7}, {%8,%9}, {%0,%1,%2,%3};"
        : "+f"(c[0]), "+f"(c[1]), "+f"(c[2]), "+f"(c[3])
        : "r"(a0), "r"(a1), "r"(a2), "r"(a3), "r"(b0), "r"(b1));
}
__device__ __forceinline__ float fast_exp2(float x) {
    float y;
    asm("ex2.approx.f32 %0, %1;" : "=f"(y) : "f"(x));
    return y;
}

// ---------------------------------------------------------------------------
// 1. LayerNorm over channel dim. x is [B, C, N]. Writes g_xn [B*N, C].
// ---------------------------------------------------------------------------
__global__ __launch_bounds__(256) void ln_kernel(const float* __restrict__ x,
                                                 const float* __restrict__ gamma,
                                                 const float* __restrict__ beta) {
    __shared__ float tile[16 * 513];
    __shared__ float psum[256];
    __shared__ float psq[256];
    __shared__ float smean[16];
    __shared__ float srstd[16];
    int t   = threadIdx.x;
    int blk = blockIdx.x;                 // 512 blocks = B * N/16
    int b   = blk >> 6;
    int n0  = (blk & 63) << 4;
    const float* xb = x + (size_t)b * EMBED * NTOK + n0;
    int nl    = t & 15;
    int cbase = t >> 4;
    float s = 0.f, sq = 0.f;
    #pragma unroll 8
    for (int k = 0; k < 32; k++) {
        int c = cbase + (k << 4);
        float v = xb[c * NTOK + nl];
        tile[nl * 513 + c] = v;
        s += v; sq += v * v;
    }
    psum[t] = s; psq[t] = sq;
    __syncthreads();
    if (t < 16) {
        float ss = 0.f, ssq = 0.f;
        #pragma unroll
        for (int g = 0; g < 16; g++) { ss += psum[t + (g << 4)]; ssq += psq[t + (g << 4)]; }
        float mu  = ss * (1.0f / EMBED);
        float var = ssq * (1.0f / EMBED) - mu * mu;
        smean[t] = mu;
        srstd[t] = rsqrtf(var + 1e-5f);
    }
    __syncthreads();
    float* dst = g_xn + (size_t)(b * NTOK + n0) * EMBED;
    #pragma unroll 8
    for (int k = 0; k < 32; k++) {
        int idx = t + (k << 8);
        int n = idx >> 9;
        int c = idx & 511;
        dst[n * EMBED + c] = (tile[n * 513 + c] - smean[n]) * srstd[n] * gamma[c] + beta[c];
    }
}

// ---------------------------------------------------------------------------
// 2. QKV GEMM (tf32 tensor cores): [8192,512] @ [512,1536] + bias,
//    scattered into g_q/g_k/g_v. 128x128 CTA tile, BK=32, warp tile 64x32.
// ---------------------------------------------------------------------------
__global__ __launch_bounds__(256, 2) void qkv_gemm(const float* __restrict__ W,
                                                   const float* __restrict__ bias) {
    __shared__ uint32_t As[128 * 36];     // [row][k], stride 36 (conflict-free frags)
    __shared__ uint32_t Bs[32 * 136];     // [k][n],  stride 136
    int t    = threadIdx.x;
    int lane = t & 31;
    int w    = t >> 5;
    int wm   = (w >> 2) * 64;             // warp row base
    int wn   = (w & 3) * 32;              // warp col base
    int bx = blockIdx.x;                  // 12
    int by = blockIdx.y;                  // 64
    const float* Ag = g_xn + (size_t)(by * 128) * EMBED;
    const float* Bg = W + bx * 128;

    // per-thread load coordinates
    int arow[4], akc[4], brow[4], bnc[4];
    #pragma unroll
    for (int i = 0; i < 4; i++) {
        int idx = t + i * 256;
        arow[i] = idx >> 3;  akc[i] = (idx & 7) << 2;   // A: 128 x 32
        brow[i] = idx >> 5;  bnc[i] = (idx & 31) << 2;  // B: 32 x 128
    }
    int lq = lane >> 2, lr = lane & 3;

    float acc[4][4][4];
    #pragma unroll
    for (int i = 0; i < 4; i++)
        #pragma unroll
        for (int j = 0; j < 4; j++)
            #pragma unroll
            for (int c = 0; c < 4; c++) acc[i][j][c] = 0.f;

    for (int k0 = 0; k0 < EMBED; k0 += 32) {
        float4 pa[4], pb[4];
        #pragma unroll
        for (int i = 0; i < 4; i++)
            pa[i] = *(const float4*)&Ag[(size_t)arow[i] * EMBED + k0 + akc[i]];
        #pragma unroll
        for (int i = 0; i < 4; i++)
            pb[i] = *(const float4*)&Bg[(size_t)(k0 + brow[i]) * 1536 + bnc[i]];
        __syncthreads();
        #pragma unroll
        for (int i = 0; i < 4; i++)
            *(uint4*)&As[arow[i] * 36 + akc[i]] = f4_to_tf32(pa[i]);
        #pragma unroll
        for (int i = 0; i < 4; i++)
            *(uint4*)&Bs[brow[i] * 136 + bnc[i]] = f4_to_tf32(pb[i]);
        __syncthreads();

        #pragma unroll
        for (int kk = 0; kk < 4; kk++) {
            int kb = kk << 3;
            uint32_t a[4][4];
            #pragma unroll
            for (int mt = 0; mt < 4; mt++) {
                int rb = wm + mt * 16;
                a[mt][0] = As[(rb + lq) * 36 + kb + lr];
                a[mt][1] = As[(rb + lq + 8) * 36 + kb + lr];
                a[mt][2] = As[(rb + lq) * 36 + kb + lr + 4];
                a[mt][3] = As[(rb + lq + 8) * 36 + kb + lr + 4];
            }
            #pragma unroll
            for (int nt = 0; nt < 4; nt++) {
                int nb = wn + nt * 8;
                uint32_t b0 = Bs[(kb + lr) * 136 + nb + lq];
                uint32_t b1 = Bs[(kb + lr + 4) * 136 + nb + lq];
                #pragma unroll
                for (int mt = 0; mt < 4; mt++)
                    mma_tf32(acc[mt][nt], a[mt][0], a[mt][1], a[mt][2], a[mt][3], b0, b1);
            }
        }
    }

    // Epilogue: scatter into g_q/g_k/g_v (+bias). col = s*512 + h*64 + d.
    #pragma unroll
    for (int nt = 0; nt < 4; nt++) {
        int col = bx * 128 + wn + nt * 8 + (lr << 1);
        int sid = col >> 9;
        int rem = col & 511;
        int h   = rem >> 6;
        int d0  = rem & 63;
        float b0 = bias[col], b1 = bias[col + 1];
        float* base = (sid == 0) ? g_q : (sid == 1) ? g_k : g_v;
        #pragma unroll
        for (int mt = 0; mt < 4; mt++) {
            int r0 = by * 128 + wm + mt * 16 + lq;
            #pragma unroll
            for (int half = 0; half < 2; half++) {
                int rr = r0 + half * 8;
                int b  = rr >> 10;
                int nb = rr & 1023;
                float2 v = make_float2(acc[mt][nt][half * 2] + b0,
                                       acc[mt][nt][half * 2 + 1] + b1);
                *(float2*)&base[(size_t)((b * NHEAD + h) * NTOK + nb) * HDIM + d0] = v;
            }
        }
    }
}

// ---------------------------------------------------------------------------
// 3. Flash attention (tf32 tensor cores). CTA = (128-query tile, b*h).
//    8 warps x 16 query rows. 16 KV tiles of 64. Online softmax in log2 domain.
// ---------------------------------------------------------------------------
__global__ __launch_bounds__(256, 2) void flash_kernel() {
    extern __shared__ uint32_t sm[];
    uint32_t* Qs = sm;                    // 128 x 68 (tf32)
    uint32_t* Ks = Qs + 128 * 68;         // 64 x 68
    uint32_t* Vs = Ks + 64 * 68;          // 64 x 72
    uint32_t* Ps = Vs + 64 * 72;          // 128 x 68
    int t    = threadIdx.x;
    int lane = t & 31;
    int w    = t >> 5;
    int lq = lane >> 2, lr = lane & 3;
    int qr = w * 16;                      // warp's query-row base (in tile)
    int qt = blockIdx.x;                  // 8
    int bh = blockIdx.y;                  // 64
    const float* Qg = g_q + (size_t)bh * NTOK * HDIM + qt * 128 * HDIM;
    const float* Kg = g_k + (size_t)bh * NTOK * HDIM;
    const float* Vg = g_v + (size_t)bh * NTOK * HDIM;

    // Q scale folds softmax 1/sqrt(d) AND log2(e) (we exponentiate with exp2)
    const float QSCALE = 0.125f * 1.4426950408889634f;
    #pragma unroll
    for (int li = 0; li < 8; li++) {
        int lin = t + (li << 8);
        int row = lin >> 4;
        int d4  = (lin & 15) << 2;
        float4 v = *(const float4*)&Qg[row * HDIM + d4];
        v.x *= QSCALE; v.y *= QSCALE; v.z *= QSCALE; v.w *= QSCALE;
        *(uint4*)&Qs[row * 68 + d4] = f4_to_tf32(v);
    }

    float m0 = -1e30f, m1 = -1e30f, l0 = 0.f, l1 = 0.f;
    float o[8][4];
    #pragma unroll
    for (int nt = 0; nt < 8; nt++)
        #pragma unroll
        for (int c = 0; c < 4; c++) o[nt][c] = 0.f;

    for (int kt = 0; kt < 16; kt++) {
        __syncthreads();   // guards K/V reuse from prev iter (and Qs at kt=0)
        const float* kb = Kg + kt * 64 * HDIM;
        const float* vb = Vg + kt * 64 * HDIM;
        #pragma unroll
        for (int li = 0; li < 4; li++) {
            int lin = t + (li << 8);
            int row = lin >> 4;
            int d4  = (lin & 15) << 2;
            *(uint4*)&Ks[row * 68 + d4] = f4_to_tf32(*(const float4*)&kb[row * HDIM + d4]);
            *(uint4*)&Vs[row * 72 + d4] = f4_to_tf32(*(const float4*)&vb[row * HDIM + d4]);
        }
        __syncthreads();

        // S = Q K^T  (warp: m16 x n64 x k64)
        float s[8][4];
        #pragma unroll
        for (int nt = 0; nt < 8; nt++)
            #pragma unroll
            for (int c = 0; c < 4; c++) s[nt][c] = 0.f;
        #pragma unroll
        for (int ks = 0; ks < 8; ks++) {
            int kbb = ks << 3;
            uint32_t a0 = Qs[(qr + lq) * 68 + kbb + lr];
            uint32_t a1 = Qs[(qr + lq + 8) * 68 + kbb + lr];
            uint32_t a2 = Qs[(qr + lq) * 68 + kbb + lr + 4];
            uint32_t a3 = Qs[(qr + lq + 8) * 68 + kbb + lr + 4];
            #pragma unroll
            for (int nt = 0; nt < 8; nt++) {
                uint32_t b0 = Ks[(nt * 8 + lq) * 68 + kbb + lr];
                uint32_t b1 = Ks[(nt * 8 + lq) * 68 + kbb + lr + 4];
                mma_tf32(s[nt], a0, a1, a2, a3, b0, b1);
            }
        }

        // Online softmax (rows r0 = qr+lq, r1 = r0+8; quad-shuffle reductions)
        float mx0 = -1e30f, mx1 = -1e30f;
        #pragma unroll
        for (int nt = 0; nt < 8; nt++) {
            mx0 = fmaxf(mx0, fmaxf(s[nt][0], s[nt][1]));
            mx1 = fmaxf(mx1, fmaxf(s[nt][2], s[nt][3]));
        }
        #pragma unroll
        for (int off = 1; off <= 2; off <<= 1) {
            mx0 = fmaxf(mx0, __shfl_xor_sync(0xFFFFFFFFu, mx0, off));
            mx1 = fmaxf(mx1, __shfl_xor_sync(0xFFFFFFFFu, mx1, off));
        }
        float mn0 = fmaxf(m0, mx0), mn1 = fmaxf(m1, mx1);
        float corr0 = fast_exp2(m0 - mn0), corr1 = fast_exp2(m1 - mn1);
        float rs0 = 0.f, rs1 = 0.f;
        int pr0 = (qr + lq) * 68 + (lr << 1);
        int pr1 = (qr + lq + 8) * 68 + (lr << 1);
        #pragma unroll
        for (int nt = 0; nt < 8; nt++) {
            float p00 = fast_exp2(s[nt][0] - mn0);
            float p01 = fast_exp2(s[nt][1] - mn0);
            float p10 = fast_exp2(s[nt][2] - mn1);
            float p11 = fast_exp2(s[nt][3] - mn1);
            rs0 += p00 + p01;
            rs1 += p10 + p11;
            uint2 u0 = make_uint2(f2tf32(p00), f2tf32(p01));
            uint2 u1 = make_uint2(f2tf32(p10), f2tf32(p11));
            *(uint2*)&Ps[pr0 + nt * 8] = u0;
            *(uint2*)&Ps[pr1 + nt * 8] = u1;
        }
        #pragma unroll
        for (int off = 1; off <= 2; off <<= 1) {
            rs0 += __shfl_xor_sync(0xFFFFFFFFu, rs0, off);
            rs1 += __shfl_xor_sync(0xFFFFFFFFu, rs1, off);
        }
        l0 = l0 * corr0 + rs0;  m0 = mn0;
        l1 = l1 * corr1 + rs1;  m1 = mn1;
        #pragma unroll
        for (int nt = 0; nt < 8; nt++) {
            o[nt][0] *= corr0; o[nt][1] *= corr0;
            o[nt][2] *= corr1; o[nt][3] *= corr1;
        }
        __syncwarp();   // Ps rows are warp-private; order STS before LDS

        // O += P V  (warp: m16 x n64(d) x k64(kv))
        #pragma unroll
        for (int ks = 0; ks < 8; ks++) {
            int kbb = ks << 3;
            uint32_t a0 = Ps[(qr + lq) * 68 + kbb + lr];
            uint32_t a1 = Ps[(qr + lq + 8) * 68 + kbb + lr];
            uint32_t a2 = Ps[(qr + lq) * 68 + kbb + lr + 4];
            uint32_t a3 = Ps[(qr + lq + 8) * 68 + kbb + lr + 4];
            #pragma unroll
            for (int nt = 0; nt < 8; nt++) {
                uint32_t b0 = Vs[(kbb + lr) * 72 + nt * 8 + lq];
                uint32_t b1 = Vs[(kbb + lr + 4) * 72 + nt * 8 + lq];
                mma_tf32(o[nt], a0, a1, a2, a3, b0, b1);
            }
        }
    }

    // Write O/l to g_o [B*N, C] (c = h*64 + d)
    int b = bh >> 3, h = bh & 7;
    float inv0 = 1.0f / l0, inv1 = 1.0f / l1;
    int r0 = qt * 128 + qr + lq;
    float* ob0 = g_o + (size_t)(b * NTOK + r0) * EMBED + h * HDIM + (lr << 1);
    float* ob1 = ob0 + 8 * EMBED;
    #pragma unroll
    for (int nt = 0; nt < 8; nt++) {
        *(float2*)&ob0[nt * 8] = make_float2(o[nt][0] * inv0, o[nt][1] * inv0);
        *(float2*)&ob1[nt * 8] = make_float2(o[nt][2] * inv1, o[nt][3] * inv1);
    }
}

// ---------------------------------------------------------------------------
// 4. Output projection (tf32): [8192,512] @ [512,512] + bias, write [B, C, N].
// ---------------------------------------------------------------------------
__global__ __launch_bounds__(256, 2) void proj_gemm(const float* __restrict__ W,
                                                    const float* __restrict__ bias,
                                                    float* __restrict__ out) {
    __shared__ uint32_t As[128 * 36];
    __shared__ uint32_t Bs[32 * 136];
    int t    = threadIdx.x;
    int lane = t & 31;
    int w    = t >> 5;
    int wm   = (w >> 2) * 64;
    int wn   = (w & 3) * 32;
    int bx = blockIdx.x;                  // 4
    int by = blockIdx.y;                  // 64
    const float* Ag = g_o + (size_t)(by * 128) * EMBED;
    const float* Bg = W + bx * 128;

    int arow[4], akc[4], brow[4], bnc[4];
    #pragma unroll
    for (int i = 0; i < 4; i++) {
        int idx = t + i * 256;
        arow[i] = idx >> 3;  akc[i] = (idx & 7) << 2;
        brow[i] = idx >> 5;  bnc[i] = (idx & 31) << 2;
    }
    int lq = lane >> 2, lr = lane & 3;

    float acc[4][4][4];
    #pragma unroll
    for (int i = 0; i < 4; i++)
        #pragma unroll
        for (int j = 0; j < 4; j++)
            #pragma unroll
            for (int c = 0; c < 4; c++) acc[i][j][c] = 0.f;

    for (int k0 = 0; k0 < EMBED; k0 += 32) {
        float4 pa[4], pb[4];
        #pragma unroll
        for (int i = 0; i < 4; i++)
            pa[i] = *(const float4*)&Ag[(size_t)arow[i] * EMBED + k0 + akc[i]];
        #pragma unroll
        for (int i = 0; i < 4; i++)
            pb[i] = *(const float4*)&Bg[(size_t)(k0 + brow[i]) * EMBED + bnc[i]];
        __syncthreads();
        #pragma unroll
        for (int i = 0; i < 4; i++)
            *(uint4*)&As[arow[i] * 36 + akc[i]] = f4_to_tf32(pa[i]);
        #pragma unroll
        for (int i = 0; i < 4; i++)
            *(uint4*)&Bs[brow[i] * 136 + bnc[i]] = f4_to_tf32(pb[i]);
        __syncthreads();

        #pragma unroll
        for (int kk = 0; kk < 4; kk++) {
            int kb = kk << 3;
            uint32_t a[4][4];
            #pragma unroll
            for (int mt = 0; mt < 4; mt++) {
                int rb = wm + mt * 16;
                a[mt][0] = As[(rb + lq) * 36 + kb + lr];
                a[mt][1] = As[(rb + lq + 8) * 36 + kb + lr];
                a[mt][2] = As[(rb + lq) * 36 + kb + lr + 4];
                a[mt][3] = As[(rb + lq + 8) * 36 + kb + lr + 4];
            }
            #pragma unroll
            for (int nt = 0; nt < 4; nt++) {
                int nb = wn + nt * 8;
                uint32_t b0 = Bs[(kb + lr) * 136 + nb + lq];
                uint32_t b1 = Bs[(kb + lr + 4) * 136 + nb + lq];
                #pragma unroll
                for (int mt = 0; mt < 4; mt++)
                    mma_tf32(acc[mt][nt], a[mt][0], a[mt][1], a[mt][2], a[mt][3], b0, b1);
            }
        }
    }

    // Epilogue: out[b, c, n] = acc + bias[c]  (transposed scatter)
    #pragma unroll
    for (int nt = 0; nt < 4; nt++) {
        int col = bx * 128 + wn + nt * 8 + (lr << 1);
        float bb0 = bias[col], bb1 = bias[col + 1];
        #pragma unroll
        for (int mt = 0; mt < 4; mt++) {
            int r0 = by * 128 + wm + mt * 16 + lq;
            #pragma unroll
            for (int half = 0; half < 2; half++) {
                int rr = r0 + half * 8;
                int b  = rr >> 10;
                int nb = rr & 1023;
                out[((size_t)b * EMBED + col) * NTOK + nb]     = acc[mt][nt][half * 2]     + bb0;
                out[((size_t)b * EMBED + col + 1) * NTOK + nb] = acc[mt][nt][half * 2 + 1] + bb1;
            }
        }
    }
}

// ---------------------------------------------------------------------------
extern "C" void kernel_launch(void* const* d_in, const int* in_sizes, int n_in,
                              void* d_out, int out_size) {
    (void)in_sizes; (void)n_in; (void)out_size;
    const float* x      = (const float*)d_in[0];
    const float* gamma  = (const float*)d_in[1];
    const float* beta   = (const float*)d_in[2];
    const float* w_qkv  = (const float*)d_in[3];
    const float* b_qkv  = (const float*)d_in[4];
    const float* w_proj = (const float*)d_in[5];
    const float* b_proj = (const float*)d_in[6];
    float* out = (float*)d_out;

    ln_kernel<<<512, 256>>>(x, gamma, beta);
    qkv_gemm<<<dim3(12, 64), 256>>>(w_qkv, b_qkv);

    const int FLASH_SMEM = (128 * 68 + 64 * 68 + 64 * 72 + 128 * 68) * 4; // 105472 B
    cudaFuncSetAttribute(flash_kernel,
                         cudaFuncAttributeMaxDynamicSharedMemorySize, FLASH_SMEM);
    flash_kernel<<<dim3(8, 64), 256, FLASH_SMEM>>>();

    proj_gemm<<<dim3(4, 64), 256>>>(w_proj, b_proj, out);
}